// round 17
// baseline (speedup 1.0000x reference)
#include <cuda_runtime.h>
#include <cuda_fp16.h>
#include <cstdint>

// Problem: B=4, C=256, HW=4096. S = Q^T K per batch; outputs S[:, :1024, :1024] + argmax rows.
// 3-segment fp16 split GEMM (branchless packed top-2) + separate fp64 fixup kernel.
#define BATCH   4
#define CDIM    256
#define HWDIM   4096
#define VIS     1024
#define KSPLIT  512            // [hi(256) | lo(256)] halfs per hw-row
#define TILE_M  64
#define TILE_N  128
#define NCHUNKS (HWDIM / TILE_N)        // 32
#define KSTEPS  24                      // 3 segs x 8 k-blocks of 32
#define TOTSTEPS (NCHUNKS * KSTEPS)     // 768
#define STAGE_BYTES 12288               // A 4KB + B 8KB
#define SM_RED  49152                   // after 4 stages
#define SM_TOTAL (SM_RED + 2048)
#define GAP_TAU 0.05f

// Scratch (allocation-free device globals).
__device__ __half g_QT[(size_t)BATCH * HWDIM * KSPLIT];
__device__ __half g_KT[(size_t)BATCH * HWDIM * KSPLIT];
__device__ float4 g_top2[(size_t)BATCH * HWDIM];   // (v1, i1bits, v2, i2bits)

typedef unsigned long long u64;

#define CP16(dst, src) \
    asm volatile("cp.async.cg.shared.global [%0], [%1], 16;" :: "r"(dst), "l"(src))
#define CP_COMMIT() asm volatile("cp.async.commit_group;" ::: "memory")
#define CP_WAIT2()  asm volatile("cp.async.wait_group 2;" ::: "memory")

__device__ __forceinline__ uint32_t smem_u32(const void* p) {
    uint32_t a;
    asm("{ .reg .u64 t; cvta.to.shared.u64 t, %1; cvt.u32.u64 %0, t; }" : "=r"(a) : "l"(p));
    return a;
}
__device__ __forceinline__ void ldsm4(uint32_t* r, uint32_t addr) {
    asm volatile("ldmatrix.sync.aligned.m8n8.x4.shared.b16 {%0,%1,%2,%3}, [%4];"
                 : "=r"(r[0]), "=r"(r[1]), "=r"(r[2]), "=r"(r[3]) : "r"(addr));
}
__device__ __forceinline__ void mma16816(float* d, const uint32_t* a, const uint32_t* b) {
    asm volatile("mma.sync.aligned.m16n8k16.row.col.f32.f16.f16.f32 "
                 "{%0,%1,%2,%3}, {%4,%5,%6,%7}, {%8,%9}, {%0,%1,%2,%3};"
                 : "+f"(d[0]), "+f"(d[1]), "+f"(d[2]), "+f"(d[3])
                 : "r"(a[0]), "r"(a[1]), "r"(a[2]), "r"(a[3]), "r"(b[0]), "r"(b[1]));
}

// Sortable (value,index) packing: larger value wins; equal value -> smaller index wins
// (first-occurrence, matching jnp.argmax). All branchless.
__device__ __forceinline__ u64 pack_vi(float v, int i) {
    unsigned u = __float_as_uint(v);
    u ^= (unsigned)((int)u >> 31) | 0x80000000u;
    return ((u64)u << 32) | (unsigned)(~i);
}
__device__ __forceinline__ float unpack_v(u64 k) {
    unsigned m = (unsigned)(k >> 32);
    m ^= (~(unsigned)((int)m >> 31)) | 0x80000000u;
    return __uint_as_float(m);
}
__device__ __forceinline__ int unpack_i(u64 k) {
    return (int)(~(unsigned)k);
}
// Branchless top-2 insert: hi = best, lo = second best.
__device__ __forceinline__ void t2ins(u64 k, u64& hi, u64& lo) {
    const u64 mx = (k > hi) ? k : hi;
    const u64 mn = (k > hi) ? hi : k;
    lo = (mn > lo) ? mn : lo;
    hi = mx;
}
__device__ __forceinline__ u64 shfl_xor_u64(u64 v, int off) {
    unsigned lo = (unsigned)v, hi = (unsigned)(v >> 32);
    lo = __shfl_xor_sync(0xffffffffu, lo, off);
    hi = __shfl_xor_sync(0xffffffffu, hi, off);
    return ((u64)hi << 32) | lo;
}

// ---- Kernel 1: transpose + fp16 hi/lo split ----
__global__ __launch_bounds__(256, 4)
void split_tp(const float* __restrict__ Q, const float* __restrict__ K)
{
    const int bz = blockIdx.z;                   // bit0 = which tensor, bits1.. = batch
    const float* src = ((bz & 1) ? K : Q) + (size_t)(bz >> 1) * CDIM * HWDIM;
    __half* dst = ((bz & 1) ? g_KT : g_QT) + (size_t)(bz >> 1) * HWDIM * KSPLIT;
    __shared__ float t[32][33];
    const int x0 = blockIdx.x * 32;              // hw
    const int y0 = blockIdx.y * 32;              // c
    const int tx = threadIdx.x & 31, ty = threadIdx.x >> 5;
#pragma unroll
    for (int j = 0; j < 4; ++j)
        t[ty + 8 * j][tx] = src[(size_t)(y0 + ty + 8 * j) * HWDIM + x0 + tx];
    __syncthreads();
#pragma unroll
    for (int j = 0; j < 4; ++j) {
        const int hw = x0 + ty + 8 * j;
        const float x = t[tx][ty + 8 * j];
        const __half hi = __float2half_rn(x);
        const __half lo = __float2half_rn(x - __half2float(hi));
        const size_t o = (size_t)hw * KSPLIT + y0 + tx;
        dst[o] = hi;
        dst[o + CDIM] = lo;
    }
}

// one cp.async stage: A 64x32 halfs (4KB) + B 128x32 halfs (8KB), swizzled 64B rows.
// 128 threads: A units tid, tid+128 -> rows r0, r0+32; B units tid+128j -> rows r0+32j.
__device__ __forceinline__ void issue_stage(
    uint32_t smb, int slot, const __half* QTb, const __half* KTb,
    int chunk, int ks, int r0, int u0, int dst0)
{
    const int seg = ks >> 3, kb = ks & 7;
    const int ca = ((seg == 2) ? CDIM : 0) + kb * 32;   // A: [hi | hi | lo]
    const int cb = ((seg == 1) ? CDIM : 0) + kb * 32;   // B: [hi | lo | hi]
    const uint32_t ab = smb + slot * STAGE_BYTES;
    const uint32_t bb = ab + 4096;
    const __half* pa = QTb + (size_t)r0 * KSPLIT + u0 * 8 + ca;
    CP16(ab + dst0, pa);
    CP16(ab + dst0 + 2048, pa + 32 * KSPLIT);
    const __half* pb = KTb + ((size_t)chunk * TILE_N + r0) * KSPLIT + u0 * 8 + cb;
#pragma unroll
    for (int j = 0; j < 4; ++j)
        CP16(bb + dst0 + j * 2048, pb + (size_t)(32 * j) * KSPLIT);
}

// ---- Kernel 2: fp16-split mma.sync GEMM, 2 CTAs/SM, branchless packed top-2 ----
__global__ __launch_bounds__(128, 2)
void gemm_fp16(float* __restrict__ Svis)
{
    extern __shared__ char smem[];
    const uint32_t smb = smem_u32(smem);
    const int tid = threadIdx.x;
    const int lane = tid & 31, wid = tid >> 5;
    const int wm = wid >> 1, wn = wid & 1;          // warp grid 2(M) x 2(N), tile 32x64
    const int b = blockIdx.y;
    const int q0 = blockIdx.x * TILE_M;

    const __half* QTb = g_QT + ((size_t)(b * HWDIM + q0)) * KSPLIT;
    const __half* KTb = g_KT + (size_t)b * HWDIM * KSPLIT;

    // loader mapping: unit i -> row i>>2, 16B-unit i&3 within 64B row.
    const int r0 = tid >> 2, u0 = tid & 3;
    const int dst0 = r0 * 64 + ((u0 ^ ((r0 >> 1) & 3)) * 16);  // swizzle xor invariant to row+32

    // ldmatrix lane geometry
    const int arow = lane & 15;
    const int auk  = (lane >> 4) & 1;
    const int brow = (lane & 7) + ((lane >> 4) & 1) * 8;
    const int buk  = (lane >> 3) & 1;

    int am[2], axor[2];
#pragma unroll
    for (int mt = 0; mt < 2; ++mt) {
        const int m = wm * 32 + mt * 16 + arow;
        am[mt] = m * 64;
        axor[mt] = (m >> 1) & 3;
    }
    int bn[4], bxor[4];
#pragma unroll
    for (int p = 0; p < 4; ++p) {
        const int n = wn * 64 + p * 16 + brow;
        bn[p] = n * 64;
        bxor[p] = (n >> 1) & 3;
    }

    const float NEG_INF = __int_as_float(0xff800000);
    // Branchless packed top-2 state: 4 row-slots (mt x h).
    u64 thi[4], tlo[4];
#pragma unroll
    for (int s = 0; s < 4; ++s) { thi[s] = pack_vi(NEG_INF, 0); tlo[s] = pack_vi(NEG_INF, 1); }

    // Prologue: 3 stages in flight
    int pf_chunk = 0, pf_ks = 0;
#pragma unroll
    for (int s = 0; s < 3; ++s) {
        issue_stage(smb, s, QTb, KTb, pf_chunk, pf_ks, r0, u0, dst0);
        CP_COMMIT();
        if (++pf_ks == KSTEPS) { pf_ks = 0; ++pf_chunk; }
    }

    int gs = 0;
    const bool visq = (q0 < VIS);

    for (int chunk = 0; chunk < NCHUNKS; ++chunk) {
        float acc[2][8][4];
#pragma unroll
        for (int mt = 0; mt < 2; ++mt)
#pragma unroll
        for (int nt = 0; nt < 8; ++nt)
#pragma unroll
        for (int e = 0; e < 4; ++e) acc[mt][nt][e] = 0.f;

        for (int ks = 0; ks < KSTEPS; ++ks, ++gs) {
            CP_WAIT2();
            __syncthreads();
            const int slot = gs & 3;
            const uint32_t ab = smb + slot * STAGE_BYTES;
            const uint32_t bb = ab + 4096;
#pragma unroll
            for (int k16 = 0; k16 < 2; ++k16) {
                uint32_t af[2][4];
#pragma unroll
                for (int mt = 0; mt < 2; ++mt) {
                    const int u = (k16 * 2 + auk) ^ axor[mt];
                    ldsm4(af[mt], ab + am[mt] + u * 16);
                }
                uint32_t bf[4][4];
#pragma unroll
                for (int p = 0; p < 4; ++p) {
                    const int u = (k16 * 2 + buk) ^ bxor[p];
                    ldsm4(bf[p], bb + bn[p] + u * 16);
                }
#pragma unroll
                for (int mt = 0; mt < 2; ++mt)
#pragma unroll
                for (int nt = 0; nt < 8; ++nt)
                    mma16816(acc[mt][nt], af[mt], &bf[nt >> 1][(nt & 1) * 2]);
            }
            if (gs + 3 < TOTSTEPS) {
                issue_stage(smb, (gs + 3) & 3, QTb, KTb, pf_chunk, pf_ks, r0, u0, dst0);
                if (++pf_ks == KSTEPS) { pf_ks = 0; ++pf_chunk; }
            }
            CP_COMMIT();
        }

        // Epilogue: branchless packed top-2 update + visible-corner store.
        const int n0 = chunk * TILE_N;
#pragma unroll
        for (int mt = 0; mt < 2; ++mt)
#pragma unroll
        for (int nt = 0; nt < 8; ++nt) {
            const int nb = n0 + wn * 64 + nt * 8 + (lane & 3) * 2;
#pragma unroll
            for (int h = 0; h < 2; ++h) {
                const int s = mt * 2 + h;
#pragma unroll
                for (int j = 0; j < 2; ++j)
                    t2ins(pack_vi(acc[mt][nt][h * 2 + j], nb + j), thi[s], tlo[s]);
            }
        }
        if (visq && n0 < VIS) {
#pragma unroll
            for (int mt = 0; mt < 2; ++mt)
#pragma unroll
            for (int h = 0; h < 2; ++h) {
                const int q = q0 + wm * 32 + mt * 16 + (lane >> 2) + h * 8;
                float* row = Svis + ((size_t)(b * VIS + q)) * VIS;
#pragma unroll
                for (int nt = 0; nt < 8; ++nt) {
                    const int n = n0 + wn * 64 + nt * 8 + (lane & 3) * 2;
                    *(float2*)(row + n) = make_float2(acc[mt][nt][h * 2], acc[mt][nt][h * 2 + 1]);
                }
            }
        }
    }

    // Cross-lane reduce (lanes sharing a row differ in bits 0-1).
#pragma unroll
    for (int s = 0; s < 4; ++s) {
#pragma unroll
        for (int off = 1; off <= 2; off <<= 1) {
            const u64 ohi = shfl_xor_u64(thi[s], off);
            const u64 olo = shfl_xor_u64(tlo[s], off);
            t2ins(ohi, thi[s], tlo[s]);
            t2ins(olo, thi[s], tlo[s]);
        }
    }
    // Cross-warp (2 wn groups) via smem.
    u64* sh_hi = (u64*)(smem + SM_RED);          // [wn][64]
    u64* sh_lo = (u64*)(smem + SM_RED + 1024);
    __syncthreads();
    if ((lane & 3) == 0) {
#pragma unroll
        for (int s = 0; s < 4; ++s) {
            const int row = wm * 32 + (s >> 1) * 16 + (s & 1) * 8 + (lane >> 2);
            sh_hi[wn * 64 + row] = thi[s];
            sh_lo[wn * 64 + row] = tlo[s];
        }
    }
    __syncthreads();
    if (tid < 64) {
        u64 hi = sh_hi[tid], lo = sh_lo[tid];
        t2ins(sh_hi[64 + tid], hi, lo);
        t2ins(sh_lo[64 + tid], hi, lo);
        g_top2[(size_t)b * HWDIM + q0 + tid] =
            make_float4(unpack_v(hi), __int_as_float(unpack_i(hi)),
                        unpack_v(lo), __int_as_float(unpack_i(lo)));
    }
}

// ---- Kernel 3: fp64 re-score of close top-2 candidates; writes H. ----
__global__ __launch_bounds__(256, 4)
void fixup_argmax(const float* __restrict__ Qo, const float* __restrict__ Ko,
                  void* __restrict__ Hout, int hmode)
{
    const int r = blockIdx.x * 256 + threadIdx.x;      // 0 .. BATCH*HWDIM-1
    const int b = r >> 12;                             // HWDIM = 4096
    const int q = r & (HWDIM - 1);
    const float4 st = g_top2[r];
    int i1 = __float_as_int(st.y);
    const int i2 = __float_as_int(st.w);
    int idx = i1;
    if (st.x - st.z < GAP_TAU) {
        const float* Qc  = Qo + (size_t)b * CDIM * HWDIM + q;
        const float* Ka  = Ko + (size_t)b * CDIM * HWDIM + i1;
        const float* Kb2 = Ko + (size_t)b * CDIM * HWDIM + i2;
        double e1 = 0.0, e2 = 0.0;
        for (int c = 0; c < CDIM; ++c) {
            const double qv = (double)Qc[(size_t)c * HWDIM];
            e1 += qv * (double)Ka[(size_t)c * HWDIM];
            e2 += qv * (double)Kb2[(size_t)c * HWDIM];
        }
        if (e2 > e1 || (e2 == e1 && i2 < i1)) idx = i2;
    }
    if (hmode == 1) ((long long*)Hout)[r] = (long long)idx;
    else            ((float*)Hout)[r] = (float)idx;
}

extern "C" void kernel_launch(void* const* d_in, const int* in_sizes, int n_in,
                              void* d_out, int out_size)
{
    const float* Q = (const float*)d_in[0];
    const float* K = (const float*)d_in[1];
    // V unused by reference outputs.

    float* Svis = (float*)d_out;
    const size_t svis_elems = (size_t)BATCH * VIS * VIS;

    int hmode;
    void* hptr;
    if (out_size == 4227072) {
        hmode = 1;
        hptr = (void*)((char*)d_out + svis_elems * sizeof(float));
    } else {
        hmode = 0;
        hptr = (void*)((float*)d_out + svis_elems);
    }

    static int attr_done = 0;
    if (!attr_done) {
        cudaFuncSetAttribute(gemm_fp16, cudaFuncAttributeMaxDynamicSharedMemorySize, SM_TOTAL);
        attr_done = 1;
    }

    split_tp<<<dim3(HWDIM / 32, CDIM / 32, 2 * BATCH), 256>>>(Q, K);
    gemm_fp16<<<dim3(HWDIM / TILE_M, BATCH), 128, SM_TOTAL>>>(Svis);
    fixup_argmax<<<(BATCH * HWDIM) / 256, 256>>>(Q, K, hptr, hmode);
}